// round 3
// baseline (speedup 1.0000x reference)
#include <cuda_runtime.h>
#include <cuda_fp16.h>
#include <math.h>
#include <stdint.h>

// Problem constants
#define NN 50000
#define EE 800000
#define FF 86
#define HH 128
#define EDD 16
#define CC 18
#define GG 64
#define NEG_SLOPE 0.2f

#define NBLK ((NN + 255) / 256)   // 196 scan blocks

// ---------------- scratch (static device globals; no allocation) ----------------
__device__ int    d_deg[NN];
__device__ int    d_cur[NN];
__device__ int    d_off[NN + 1];
__device__ int    d_bsum[256];
__device__ int    d_srcs[EE];
__device__ float  d_ea1[EE];
__device__ float  d_ea2[EE];
__device__ float  d_aw[EE];
__device__ __half d_hh[(size_t)NN * HH];  // fp16 transformed features (gather source)
__device__ float  d_o[(size_t)NN * HH];   // layer output (fp32, gemm input)
__device__ float  d_hs[NN];
__device__ float  d_hd[NN];
__device__ float  d_v1[EDD];
__device__ float  d_v2[EDD];
__device__ float  d_pool[GG * HH];

// ---------------- small helpers ----------------
__device__ __forceinline__ float to_tf32(float x) {
    uint32_t u;
    asm("cvt.rna.tf32.f32 %0, %1;" : "=r"(u) : "f"(x));
    return __uint_as_float(u);
}

__device__ __forceinline__ int warp_iscan(int x, int lane) {
#pragma unroll
    for (int o = 1; o < 32; o <<= 1) {
        int y = __shfl_up_sync(0xffffffffu, x, o);
        if (lane >= o) x += y;
    }
    return x;
}

// ---------------- kernels ----------------

// zero counters/pool + precompute v1 = We1@ae1, v2 = We2@ae2
__global__ void init_k(const float* __restrict__ We1, const float* __restrict__ ae1,
                       const float* __restrict__ We2, const float* __restrict__ ae2) {
    int i = blockIdx.x * blockDim.x + threadIdx.x;
    if (i < NN) { d_deg[i] = 0; d_cur[i] = 0; }
    if (i < GG * HH) d_pool[i] = 0.0f;
    if (blockIdx.x == 0) {
        int t = threadIdx.x;
        if (t < EDD) {
            float s = 0.f;
            for (int h = 0; h < HH; h++) s += We1[t * HH + h] * ae1[h];
            d_v1[t] = s;
        } else if (t < 2 * EDD) {
            int k = t - EDD;
            float s = 0.f;
            for (int h = 0; h < HH; h++) s += We2[k * HH + h] * ae2[h];
            d_v2[k] = s;
        }
    }
}

__global__ void hist_k(const int* __restrict__ dst) {
    int e = blockIdx.x * blockDim.x + threadIdx.x;
    if (e < EE) atomicAdd(&d_deg[dst[e]], 1);
}

// ---- 3-phase multi-block exclusive scan of d_deg -> d_off ----
__global__ void scan1_k() {
    __shared__ int ws[8];
    int t = threadIdx.x, lane = t & 31, warp = t >> 5;
    int i = blockIdx.x * 256 + t;
    int v = (i < NN) ? d_deg[i] : 0;
    int wi = warp_iscan(v, lane);
    if (lane == 31) ws[warp] = wi;
    __syncthreads();
    if (warp == 0) {
        int s = (lane < 8) ? ws[lane] : 0;
        int si = warp_iscan(s, lane);
        if (lane < 8) ws[lane] = si - s;  // exclusive
    }
    __syncthreads();
    int excl = ws[warp] + wi - v;
    if (i < NN) d_off[i] = excl;
    if (t == 255) d_bsum[blockIdx.x] = ws[7] + wi;  // block total
}

__global__ void scan2_k() {
    __shared__ int ws[8];
    int t = threadIdx.x, lane = t & 31, warp = t >> 5;
    int v = (t < NBLK) ? d_bsum[t] : 0;
    int wi = warp_iscan(v, lane);
    if (lane == 31) ws[warp] = wi;
    __syncthreads();
    if (warp == 0) {
        int s = (lane < 8) ? ws[lane] : 0;
        int si = warp_iscan(s, lane);
        if (lane < 8) ws[lane] = si - s;
    }
    __syncthreads();
    int incl = ws[warp] + wi;
    if (t < NBLK) d_bsum[t] = incl - v;   // exclusive
    if (t == NBLK - 1) d_off[NN] = incl;  // grand total (== EE)
}

__global__ void scan3_k() {
    int i = blockIdx.x * 256 + threadIdx.x;
    if (i < NN) d_off[i] += d_bsum[blockIdx.x];
}

// scatter edges into CSR-by-dst; also compute per-edge scalars for both layers
__global__ void scatter_k(const int* __restrict__ src, const int* __restrict__ dst,
                          const float* __restrict__ edge_attr) {
    int e = blockIdx.x * blockDim.x + threadIdx.x;
    if (e >= EE) return;
    int d = dst[e];
    int p = d_off[d] + atomicAdd(&d_cur[d], 1);
    d_srcs[p] = src[e];
    const float4* ea = (const float4*)(edge_attr + (size_t)e * EDD);
    float s1 = 0.f, s2 = 0.f;
#pragma unroll
    for (int q = 0; q < 4; q++) {
        float4 xv = ea[q];
        s1 += xv.x * d_v1[q * 4 + 0] + xv.y * d_v1[q * 4 + 1]
            + xv.z * d_v1[q * 4 + 2] + xv.w * d_v1[q * 4 + 3];
        s2 += xv.x * d_v2[q * 4 + 0] + xv.y * d_v2[q * 4 + 1]
            + xv.z * d_v2[q * 4 + 2] + xv.w * d_v2[q * 4 + 3];
    }
    d_ea1[p] = s1;
    d_ea2[p] = s2;
}

// ---------------- tf32 GEMM + fused epilogue ----------------
// hh[M,128](fp16) = A[M,K] @ B[K,128]; hs = hh@a_src; hd = hh@a_dst (fp32 from accs)
// block tile 128x128, K chunked by 32; 8 warps, warp tile 64x32 (m16n8k8 atoms)
#define KC 32
__global__ __launch_bounds__(256, 2) void gemm_fused_k(const float* __restrict__ A,
                                                       const float* __restrict__ B,
                                                       const float* __restrict__ a_src,
                                                       const float* __restrict__ a_dst,
                                                       __half* __restrict__ Chh,
                                                       int M, int K) {
    __shared__ float As[128][KC + 4];    // stride 36
    __shared__ float Bs[KC][HH + 4];     // stride 132
    __shared__ float hs_s[128], hd_s[128];
    int tid = threadIdx.x;
    int wid = tid >> 5, lane = tid & 31;
    int mw = wid >> 2, nw = wid & 3;          // 2 x 4 warp grid
    int gp = lane >> 2, t4 = lane & 3;        // fragment coords
    int rowBase = blockIdx.x * 128;

    if (tid < 128) { hs_s[tid] = 0.f; hd_s[tid] = 0.f; }

    float acc[4][4][4];
#pragma unroll
    for (int a = 0; a < 4; a++)
#pragma unroll
        for (int b = 0; b < 4; b++)
#pragma unroll
            for (int c = 0; c < 4; c++) acc[a][b][c] = 0.f;

    int nChunks = (K + KC - 1) / KC;
    for (int kc = 0; kc < nChunks; kc++) {
        int kbase = kc * KC;
        {
            int rl = tid >> 3;   // 0..31
            int kl = tid & 7;    // 0..7
#pragma unroll
            for (int i = 0; i < 4; i++) {
                int r = rl + i * 32;
                int grow = rowBase + r;
                const float* arow = A + (size_t)grow * K;
#pragma unroll
                for (int j = 0; j < 4; j++) {
                    int k = kl + j * 8;
                    int gk = kbase + k;
                    float v = (grow < M && gk < K) ? arow[gk] : 0.f;
                    As[r][k] = to_tf32(v);
                }
            }
        }
        {
#pragma unroll
            for (int i = 0; i < 4; i++) {
                int idx = tid + 256 * i;
                int k = idx >> 5, f4 = idx & 31;
                int gk = kbase + k;
                float4 bv = make_float4(0.f, 0.f, 0.f, 0.f);
                if (gk < K) bv = *(const float4*)&B[(size_t)gk * HH + f4 * 4];
                Bs[k][f4 * 4 + 0] = to_tf32(bv.x);
                Bs[k][f4 * 4 + 1] = to_tf32(bv.y);
                Bs[k][f4 * 4 + 2] = to_tf32(bv.z);
                Bs[k][f4 * 4 + 3] = to_tf32(bv.w);
            }
        }
        __syncthreads();
#pragma unroll
        for (int ka = 0; ka < 4; ka++) {
            int kb = ka * 8;
            uint32_t af[4][4];
#pragma unroll
            for (int mi = 0; mi < 4; mi++) {
                int r0 = mw * 64 + mi * 16 + gp;
                af[mi][0] = __float_as_uint(As[r0][kb + t4]);
                af[mi][1] = __float_as_uint(As[r0 + 8][kb + t4]);
                af[mi][2] = __float_as_uint(As[r0][kb + t4 + 4]);
                af[mi][3] = __float_as_uint(As[r0 + 8][kb + t4 + 4]);
            }
            uint32_t bf[4][2];
#pragma unroll
            for (int ni = 0; ni < 4; ni++) {
                int c0 = nw * 32 + ni * 8 + gp;
                bf[ni][0] = __float_as_uint(Bs[kb + t4][c0]);
                bf[ni][1] = __float_as_uint(Bs[kb + t4 + 4][c0]);
            }
#pragma unroll
            for (int mi = 0; mi < 4; mi++)
#pragma unroll
                for (int ni = 0; ni < 4; ni++) {
                    asm volatile(
                        "mma.sync.aligned.m16n8k8.row.col.f32.tf32.tf32.f32 "
                        "{%0,%1,%2,%3}, {%4,%5,%6,%7}, {%8,%9}, {%0,%1,%2,%3};"
                        : "+f"(acc[mi][ni][0]), "+f"(acc[mi][ni][1]),
                          "+f"(acc[mi][ni][2]), "+f"(acc[mi][ni][3])
                        : "r"(af[mi][0]), "r"(af[mi][1]), "r"(af[mi][2]), "r"(af[mi][3]),
                          "r"(bf[ni][0]), "r"(bf[ni][1]));
                }
        }
        __syncthreads();
    }

    // epilogue: write fp16 C; accumulate hs/hd partials into smem
    float avs[8], avd[8];
#pragma unroll
    for (int ni = 0; ni < 4; ni++) {
        int c = nw * 32 + ni * 8 + 2 * t4;
        avs[ni * 2]     = __ldg(&a_src[c]);
        avs[ni * 2 + 1] = __ldg(&a_src[c + 1]);
        avd[ni * 2]     = __ldg(&a_dst[c]);
        avd[ni * 2 + 1] = __ldg(&a_dst[c + 1]);
    }
#pragma unroll
    for (int mi = 0; mi < 4; mi++) {
#pragma unroll
        for (int hf = 0; hf < 2; hf++) {
            int rl = mw * 64 + mi * 16 + gp + 8 * hf;
            int r = rowBase + rl;
            float ss = 0.f, dd = 0.f;
#pragma unroll
            for (int ni = 0; ni < 4; ni++) {
                int c = nw * 32 + ni * 8 + 2 * t4;
                float v0 = acc[mi][ni][2 * hf + 0];
                float v1 = acc[mi][ni][2 * hf + 1];
                ss += v0 * avs[ni * 2] + v1 * avs[ni * 2 + 1];
                dd += v0 * avd[ni * 2] + v1 * avd[ni * 2 + 1];
                if (r < M)
                    *(__half2*)&Chh[(size_t)r * HH + c] =
                        __floats2half2_rn(v0, v1);
            }
            atomicAdd(&hs_s[rl], ss);
            atomicAdd(&hd_s[rl], dd);
        }
    }
    __syncthreads();
    if (tid < 128) {
        int r = rowBase + tid;
        if (r < M) { d_hs[r] = hs_s[tid]; d_hd[r] = hd_s[tid]; }
    }
}

// one warp per dst node: logits -> segment softmax -> weighted fp16 gather
// POOL=false: out[n,:] = relu(sum + bias)   POOL=true: atomicMax into d_pool[batch[n]]
template <bool POOL>
__global__ void attn_agg_k(const float* __restrict__ ea, const float* __restrict__ bias,
                           float* __restrict__ out, const int* __restrict__ batch) {
    int gt = blockIdx.x * blockDim.x + threadIdx.x;
    int n = gt >> 5, lane = gt & 31;
    if (n >= NN) return;
    int b0 = d_off[n], b1 = d_off[n + 1];
    float hdn = d_hd[n];

    float lm = -1e30f;
    for (int j = b0 + lane; j < b1; j += 32) {
        float a = d_hs[d_srcs[j]] + hdn + ea[j];
        a = (a > 0.f) ? a : NEG_SLOPE * a;
        d_aw[j] = a;
        lm = fmaxf(lm, a);
    }
#pragma unroll
    for (int o = 16; o; o >>= 1) lm = fmaxf(lm, __shfl_xor_sync(0xffffffffu, lm, o));

    float ls = 0.f;
    for (int j = b0 + lane; j < b1; j += 32) {
        float ex = __expf(d_aw[j] - lm);
        d_aw[j] = ex;
        ls += ex;
    }
#pragma unroll
    for (int o = 16; o; o >>= 1) ls += __shfl_xor_sync(0xffffffffu, ls, o);
    float inv = 1.f / fmaxf(ls, 1e-16f);

    __syncwarp();

    // weighted gather: lane handles 4 contiguous features (8 bytes fp16)
    float4 acc = make_float4(0.f, 0.f, 0.f, 0.f);
    int fo = lane << 2;
#pragma unroll 4
    for (int j = b0; j < b1; j++) {
        float w = d_aw[j] * inv;
        int s = d_srcs[j];
        uint2 raw = *(const uint2*)(d_hh + (size_t)s * HH + fo);
        float2 f0 = __half22float2(*(__half2*)&raw.x);
        float2 f1 = __half22float2(*(__half2*)&raw.y);
        acc.x += w * f0.x; acc.y += w * f0.y; acc.z += w * f1.x; acc.w += w * f1.y;
    }
    float4 bv = *(const float4*)(bias + fo);
    float4 o4;
    o4.x = fmaxf(acc.x + bv.x, 0.f);
    o4.y = fmaxf(acc.y + bv.y, 0.f);
    o4.z = fmaxf(acc.z + bv.z, 0.f);
    o4.w = fmaxf(acc.w + bv.w, 0.f);
    if (POOL) {
        int g = batch[n];
        int* pp = (int*)&d_pool[g * HH + fo];
        atomicMax(pp + 0, __float_as_int(o4.x));
        atomicMax(pp + 1, __float_as_int(o4.y));
        atomicMax(pp + 2, __float_as_int(o4.z));
        atomicMax(pp + 3, __float_as_int(o4.w));
    } else {
        *(float4*)(out + (size_t)n * HH + fo) = o4;
    }
}

// classifier + log_softmax: one warp per graph
__global__ void head_k(const float* __restrict__ Wl, const float* __restrict__ bl,
                       float* __restrict__ out) {
    int g = blockIdx.x;
    int lane = threadIdx.x;
    float logit = -INFINITY;
    if (lane < CC) {
        float s = bl[lane];
        const float* pr = d_pool + g * HH;
        for (int k = 0; k < HH; k++) s += pr[k] * Wl[k * CC + lane];
        logit = s;
    }
    float m = logit;
#pragma unroll
    for (int o = 16; o; o >>= 1) m = fmaxf(m, __shfl_xor_sync(0xffffffffu, m, o));
    float e = (lane < CC) ? __expf(logit - m) : 0.f;
    float se = e;
#pragma unroll
    for (int o = 16; o; o >>= 1) se += __shfl_xor_sync(0xffffffffu, se, o);
    float lse = m + logf(se);
    if (lane < CC) out[g * CC + lane] = logit - lse;
}

// ---------------- launch ----------------
extern "C" void kernel_launch(void* const* d_in, const int* in_sizes, int n_in,
                              void* d_out, int out_size) {
    const float* x         = (const float*)d_in[0];
    const int*   eidx      = (const int*)d_in[1];
    const float* edge_attr = (const float*)d_in[2];
    const int*   batch     = (const int*)d_in[3];
    const float* W1  = (const float*)d_in[4];
    const float* We1 = (const float*)d_in[5];
    const float* as1 = (const float*)d_in[6];
    const float* ad1 = (const float*)d_in[7];
    const float* ae1 = (const float*)d_in[8];
    const float* b1  = (const float*)d_in[9];
    const float* W2  = (const float*)d_in[10];
    const float* We2 = (const float*)d_in[11];
    const float* as2 = (const float*)d_in[12];
    const float* ad2 = (const float*)d_in[13];
    const float* ae2 = (const float*)d_in[14];
    const float* b2  = (const float*)d_in[15];
    const float* Wl  = (const float*)d_in[16];
    const float* bl  = (const float*)d_in[17];
    float* out = (float*)d_out;

    const int* srcp = eidx;
    const int* dstp = eidx + EE;

    __half* hhbuf; cudaGetSymbolAddress((void**)&hhbuf, d_hh);
    float*  obuf;  cudaGetSymbolAddress((void**)&obuf, d_o);
    float*  ea1b;  cudaGetSymbolAddress((void**)&ea1b, d_ea1);
    float*  ea2b;  cudaGetSymbolAddress((void**)&ea2b, d_ea2);

    // ---- CSR build + per-edge scalars ----
    init_k<<<(NN + 255) / 256, 256>>>(We1, ae1, We2, ae2);
    hist_k<<<(EE + 255) / 256, 256>>>(dstp);
    scan1_k<<<NBLK, 256>>>();
    scan2_k<<<1, 256>>>();
    scan3_k<<<NBLK, 256>>>();
    scatter_k<<<(EE + 255) / 256, 256>>>(srcp, dstp, edge_attr);

    const int warps_grid = (NN * 32 + 255) / 256;

    // ---- layer 1 ----
    gemm_fused_k<<<(NN + 127) / 128, 256>>>(x, W1, as1, ad1, hhbuf, NN, FF);
    attn_agg_k<false><<<warps_grid, 256>>>(ea1b, b1, obuf, batch);

    // ---- layer 2 (pool fused into aggregation) ----
    gemm_fused_k<<<(NN + 127) / 128, 256>>>(obuf, W2, as2, ad2, hhbuf, NN, HH);
    attn_agg_k<true><<<warps_grid, 256>>>(ea2b, b2, nullptr, batch);

    // ---- head ----
    head_k<<<GG, 32>>>(Wl, bl, out);
}

// round 4
// speedup vs baseline: 1.0001x; 1.0001x over previous
#include <cuda_runtime.h>
#include <cuda_fp16.h>
#include <math.h>
#include <stdint.h>

// Problem constants
#define NN 50000
#define EE 800000
#define FF 86
#define HH 128
#define EDD 16
#define CC 18
#define GG 64
#define NEG_SLOPE 0.2f

#define NBLK ((NN + 255) / 256)   // 196 scan blocks

// ---------------- scratch (static device globals; no allocation) ----------------
__device__ int    d_deg[NN];
__device__ int    d_cur[NN];
__device__ int    d_off[NN + 1];
__device__ int    d_bsum[256];
__device__ int    d_srcs[EE];
__device__ float  d_ea1[EE];
__device__ float  d_ea2[EE];
__device__ float  d_aw[EE];
__device__ __half d_hh[(size_t)NN * HH];  // fp16 transformed features (gather source)
__device__ float  d_o[(size_t)NN * HH];   // layer output (fp32, gemm input)
__device__ float  d_hs[NN];
__device__ float  d_hd[NN];
__device__ float  d_v1[EDD];
__device__ float  d_v2[EDD];
__device__ float  d_pool[GG * HH];

// ---------------- small helpers ----------------
__device__ __forceinline__ float to_tf32(float x) {
    uint32_t u;
    asm("cvt.rna.tf32.f32 %0, %1;" : "=r"(u) : "f"(x));
    return __uint_as_float(u);
}

__device__ __forceinline__ int warp_iscan(int x, int lane) {
#pragma unroll
    for (int o = 1; o < 32; o <<= 1) {
        int y = __shfl_up_sync(0xffffffffu, x, o);
        if (lane >= o) x += y;
    }
    return x;
}

// ---------------- kernels ----------------

// zero counters/pool + precompute v1 = We1@ae1, v2 = We2@ae2
__global__ void init_k(const float* __restrict__ We1, const float* __restrict__ ae1,
                       const float* __restrict__ We2, const float* __restrict__ ae2) {
    int i = blockIdx.x * blockDim.x + threadIdx.x;
    if (i < NN) { d_deg[i] = 0; d_cur[i] = 0; }
    if (i < GG * HH) d_pool[i] = 0.0f;
    if (blockIdx.x == 0) {
        int t = threadIdx.x;
        if (t < EDD) {
            float s = 0.f;
            for (int h = 0; h < HH; h++) s += We1[t * HH + h] * ae1[h];
            d_v1[t] = s;
        } else if (t < 2 * EDD) {
            int k = t - EDD;
            float s = 0.f;
            for (int h = 0; h < HH; h++) s += We2[k * HH + h] * ae2[h];
            d_v2[k] = s;
        }
    }
}

__global__ void hist_k(const int* __restrict__ dst) {
    int e = blockIdx.x * blockDim.x + threadIdx.x;
    if (e < EE) atomicAdd(&d_deg[dst[e]], 1);
}

// ---- 3-phase multi-block exclusive scan of d_deg -> d_off ----
__global__ void scan1_k() {
    __shared__ int ws[8];
    int t = threadIdx.x, lane = t & 31, warp = t >> 5;
    int i = blockIdx.x * 256 + t;
    int v = (i < NN) ? d_deg[i] : 0;
    int wi = warp_iscan(v, lane);
    if (lane == 31) ws[warp] = wi;
    __syncthreads();
    if (warp == 0) {
        int s = (lane < 8) ? ws[lane] : 0;
        int si = warp_iscan(s, lane);
        if (lane < 8) ws[lane] = si - s;  // exclusive
    }
    __syncthreads();
    int excl = ws[warp] + wi - v;
    if (i < NN) d_off[i] = excl;
    if (t == 255) d_bsum[blockIdx.x] = ws[7] + wi;  // block total
}

__global__ void scan2_k() {
    __shared__ int ws[8];
    int t = threadIdx.x, lane = t & 31, warp = t >> 5;
    int v = (t < NBLK) ? d_bsum[t] : 0;
    int wi = warp_iscan(v, lane);
    if (lane == 31) ws[warp] = wi;
    __syncthreads();
    if (warp == 0) {
        int s = (lane < 8) ? ws[lane] : 0;
        int si = warp_iscan(s, lane);
        if (lane < 8) ws[lane] = si - s;
    }
    __syncthreads();
    int incl = ws[warp] + wi;
    if (t < NBLK) d_bsum[t] = incl - v;   // exclusive
    if (t == NBLK - 1) d_off[NN] = incl;  // grand total (== EE)
}

__global__ void scan3_k() {
    int i = blockIdx.x * 256 + threadIdx.x;
    if (i < NN) d_off[i] += d_bsum[blockIdx.x];
}

// scatter edges into CSR-by-dst; also compute per-edge scalars for both layers
__global__ void scatter_k(const int* __restrict__ src, const int* __restrict__ dst,
                          const float* __restrict__ edge_attr) {
    int e = blockIdx.x * blockDim.x + threadIdx.x;
    if (e >= EE) return;
    int d = dst[e];
    int p = d_off[d] + atomicAdd(&d_cur[d], 1);
    d_srcs[p] = src[e];
    const float4* ea = (const float4*)(edge_attr + (size_t)e * EDD);
    float s1 = 0.f, s2 = 0.f;
#pragma unroll
    for (int q = 0; q < 4; q++) {
        float4 xv = ea[q];
        s1 += xv.x * d_v1[q * 4 + 0] + xv.y * d_v1[q * 4 + 1]
            + xv.z * d_v1[q * 4 + 2] + xv.w * d_v1[q * 4 + 3];
        s2 += xv.x * d_v2[q * 4 + 0] + xv.y * d_v2[q * 4 + 1]
            + xv.z * d_v2[q * 4 + 2] + xv.w * d_v2[q * 4 + 3];
    }
    d_ea1[p] = s1;
    d_ea2[p] = s2;
}

// ---------------- tf32 GEMM + fused epilogue ----------------
// hh[M,128](fp16) = A[M,K] @ B[K,128]; hs = hh@a_src; hd = hh@a_dst (fp32 from accs)
// block tile 128x128, K chunked by 32; 8 warps, warp tile 64x32 (m16n8k8 atoms)
// NOTE: no min-blocks occupancy hint — forcing 2 CTAs/SM caps regs at 128 and
// spills the 64-reg accumulator into the MMA mainloop (R3 regression).
#define KC 32
__global__ __launch_bounds__(256) void gemm_fused_k(const float* __restrict__ A,
                                                    const float* __restrict__ B,
                                                    const float* __restrict__ a_src,
                                                    const float* __restrict__ a_dst,
                                                    __half* __restrict__ Chh,
                                                    int M, int K) {
    __shared__ float As[128][KC + 4];    // stride 36
    __shared__ float Bs[KC][HH + 4];     // stride 132
    __shared__ float hs_s[128], hd_s[128];
    int tid = threadIdx.x;
    int wid = tid >> 5, lane = tid & 31;
    int mw = wid >> 2, nw = wid & 3;          // 2 x 4 warp grid
    int gp = lane >> 2, t4 = lane & 3;        // fragment coords
    int rowBase = blockIdx.x * 128;

    if (tid < 128) { hs_s[tid] = 0.f; hd_s[tid] = 0.f; }

    float acc[4][4][4];
#pragma unroll
    for (int a = 0; a < 4; a++)
#pragma unroll
        for (int b = 0; b < 4; b++)
#pragma unroll
            for (int c = 0; c < 4; c++) acc[a][b][c] = 0.f;

    int nChunks = (K + KC - 1) / KC;
    for (int kc = 0; kc < nChunks; kc++) {
        int kbase = kc * KC;
        {
            int rl = tid >> 3;   // 0..31
            int kl = tid & 7;    // 0..7
#pragma unroll
            for (int i = 0; i < 4; i++) {
                int r = rl + i * 32;
                int grow = rowBase + r;
                const float* arow = A + (size_t)grow * K;
#pragma unroll
                for (int j = 0; j < 4; j++) {
                    int k = kl + j * 8;
                    int gk = kbase + k;
                    float v = (grow < M && gk < K) ? arow[gk] : 0.f;
                    As[r][k] = to_tf32(v);
                }
            }
        }
        {
#pragma unroll
            for (int i = 0; i < 4; i++) {
                int idx = tid + 256 * i;
                int k = idx >> 5, f4 = idx & 31;
                int gk = kbase + k;
                float4 bv = make_float4(0.f, 0.f, 0.f, 0.f);
                if (gk < K) bv = *(const float4*)&B[(size_t)gk * HH + f4 * 4];
                Bs[k][f4 * 4 + 0] = to_tf32(bv.x);
                Bs[k][f4 * 4 + 1] = to_tf32(bv.y);
                Bs[k][f4 * 4 + 2] = to_tf32(bv.z);
                Bs[k][f4 * 4 + 3] = to_tf32(bv.w);
            }
        }
        __syncthreads();
#pragma unroll
        for (int ka = 0; ka < 4; ka++) {
            int kb = ka * 8;
            uint32_t af[4][4];
#pragma unroll
            for (int mi = 0; mi < 4; mi++) {
                int r0 = mw * 64 + mi * 16 + gp;
                af[mi][0] = __float_as_uint(As[r0][kb + t4]);
                af[mi][1] = __float_as_uint(As[r0 + 8][kb + t4]);
                af[mi][2] = __float_as_uint(As[r0][kb + t4 + 4]);
                af[mi][3] = __float_as_uint(As[r0 + 8][kb + t4 + 4]);
            }
            uint32_t bf[4][2];
#pragma unroll
            for (int ni = 0; ni < 4; ni++) {
                int c0 = nw * 32 + ni * 8 + gp;
                bf[ni][0] = __float_as_uint(Bs[kb + t4][c0]);
                bf[ni][1] = __float_as_uint(Bs[kb + t4 + 4][c0]);
            }
#pragma unroll
            for (int mi = 0; mi < 4; mi++)
#pragma unroll
                for (int ni = 0; ni < 4; ni++) {
                    asm volatile(
                        "mma.sync.aligned.m16n8k8.row.col.f32.tf32.tf32.f32 "
                        "{%0,%1,%2,%3}, {%4,%5,%6,%7}, {%8,%9}, {%0,%1,%2,%3};"
                        : "+f"(acc[mi][ni][0]), "+f"(acc[mi][ni][1]),
                          "+f"(acc[mi][ni][2]), "+f"(acc[mi][ni][3])
                        : "r"(af[mi][0]), "r"(af[mi][1]), "r"(af[mi][2]), "r"(af[mi][3]),
                          "r"(bf[ni][0]), "r"(bf[ni][1]));
                }
        }
        __syncthreads();
    }

    // epilogue: write fp16 C; accumulate hs/hd partials into smem
    float avs[8], avd[8];
#pragma unroll
    for (int ni = 0; ni < 4; ni++) {
        int c = nw * 32 + ni * 8 + 2 * t4;
        avs[ni * 2]     = __ldg(&a_src[c]);
        avs[ni * 2 + 1] = __ldg(&a_src[c + 1]);
        avd[ni * 2]     = __ldg(&a_dst[c]);
        avd[ni * 2 + 1] = __ldg(&a_dst[c + 1]);
    }
#pragma unroll
    for (int mi = 0; mi < 4; mi++) {
#pragma unroll
        for (int hf = 0; hf < 2; hf++) {
            int rl = mw * 64 + mi * 16 + gp + 8 * hf;
            int r = rowBase + rl;
            float ss = 0.f, dd = 0.f;
#pragma unroll
            for (int ni = 0; ni < 4; ni++) {
                int c = nw * 32 + ni * 8 + 2 * t4;
                float v0 = acc[mi][ni][2 * hf + 0];
                float v1 = acc[mi][ni][2 * hf + 1];
                ss += v0 * avs[ni * 2] + v1 * avs[ni * 2 + 1];
                dd += v0 * avd[ni * 2] + v1 * avd[ni * 2 + 1];
                if (r < M)
                    *(__half2*)&Chh[(size_t)r * HH + c] =
                        __floats2half2_rn(v0, v1);
            }
            atomicAdd(&hs_s[rl], ss);
            atomicAdd(&hd_s[rl], dd);
        }
    }
    __syncthreads();
    if (tid < 128) {
        int r = rowBase + tid;
        if (r < M) { d_hs[r] = hs_s[tid]; d_hd[r] = hd_s[tid]; }
    }
}

// one warp per dst node: logits -> segment softmax -> weighted fp16 gather
// POOL=false: out[n,:] = relu(sum + bias)   POOL=true: atomicMax into d_pool[batch[n]]
template <bool POOL>
__global__ void attn_agg_k(const float* __restrict__ ea, const float* __restrict__ bias,
                           float* __restrict__ out, const int* __restrict__ batch) {
    int gt = blockIdx.x * blockDim.x + threadIdx.x;
    int n = gt >> 5, lane = gt & 31;
    if (n >= NN) return;
    int b0 = d_off[n], b1 = d_off[n + 1];
    float hdn = d_hd[n];

    float lm = -1e30f;
    for (int j = b0 + lane; j < b1; j += 32) {
        float a = d_hs[d_srcs[j]] + hdn + ea[j];
        a = (a > 0.f) ? a : NEG_SLOPE * a;
        d_aw[j] = a;
        lm = fmaxf(lm, a);
    }
#pragma unroll
    for (int o = 16; o; o >>= 1) lm = fmaxf(lm, __shfl_xor_sync(0xffffffffu, lm, o));

    float ls = 0.f;
    for (int j = b0 + lane; j < b1; j += 32) {
        float ex = __expf(d_aw[j] - lm);
        d_aw[j] = ex;
        ls += ex;
    }
#pragma unroll
    for (int o = 16; o; o >>= 1) ls += __shfl_xor_sync(0xffffffffu, ls, o);
    float inv = 1.f / fmaxf(ls, 1e-16f);

    __syncwarp();

    // weighted gather: lane handles 4 contiguous features (8 bytes fp16)
    float4 acc = make_float4(0.f, 0.f, 0.f, 0.f);
    int fo = lane << 2;
#pragma unroll 4
    for (int j = b0; j < b1; j++) {
        float w = d_aw[j] * inv;
        int s = d_srcs[j];
        uint2 raw = *(const uint2*)(d_hh + (size_t)s * HH + fo);
        float2 f0 = __half22float2(*(__half2*)&raw.x);
        float2 f1 = __half22float2(*(__half2*)&raw.y);
        acc.x += w * f0.x; acc.y += w * f0.y; acc.z += w * f1.x; acc.w += w * f1.y;
    }
    float4 bv = *(const float4*)(bias + fo);
    float4 o4;
    o4.x = fmaxf(acc.x + bv.x, 0.f);
    o4.y = fmaxf(acc.y + bv.y, 0.f);
    o4.z = fmaxf(acc.z + bv.z, 0.f);
    o4.w = fmaxf(acc.w + bv.w, 0.f);
    if (POOL) {
        int g = batch[n];
        int* pp = (int*)&d_pool[g * HH + fo];
        atomicMax(pp + 0, __float_as_int(o4.x));
        atomicMax(pp + 1, __float_as_int(o4.y));
        atomicMax(pp + 2, __float_as_int(o4.z));
        atomicMax(pp + 3, __float_as_int(o4.w));
    } else {
        *(float4*)(out + (size_t)n * HH + fo) = o4;
    }
}

// classifier + log_softmax: one warp per graph
__global__ void head_k(const float* __restrict__ Wl, const float* __restrict__ bl,
                       float* __restrict__ out) {
    int g = blockIdx.x;
    int lane = threadIdx.x;
    float logit = -INFINITY;
    if (lane < CC) {
        float s = bl[lane];
        const float* pr = d_pool + g * HH;
        for (int k = 0; k < HH; k++) s += pr[k] * Wl[k * CC + lane];
        logit = s;
    }
    float m = logit;
#pragma unroll
    for (int o = 16; o; o >>= 1) m = fmaxf(m, __shfl_xor_sync(0xffffffffu, m, o));
    float e = (lane < CC) ? __expf(logit - m) : 0.f;
    float se = e;
#pragma unroll
    for (int o = 16; o; o >>= 1) se += __shfl_xor_sync(0xffffffffu, se, o);
    float lse = m + logf(se);
    if (lane < CC) out[g * CC + lane] = logit - lse;
}

// ---------------- launch ----------------
extern "C" void kernel_launch(void* const* d_in, const int* in_sizes, int n_in,
                              void* d_out, int out_size) {
    const float* x         = (const float*)d_in[0];
    const int*   eidx      = (const int*)d_in[1];
    const float* edge_attr = (const float*)d_in[2];
    const int*   batch     = (const int*)d_in[3];
    const float* W1  = (const float*)d_in[4];
    const float* We1 = (const float*)d_in[5];
    const float* as1 = (const float*)d_in[6];
    const float* ad1 = (const float*)d_in[7];
    const float* ae1 = (const float*)d_in[8];
    const float* b1  = (const float*)d_in[9];
    const float* W2  = (const float*)d_in[10];
    const float* We2 = (const float*)d_in[11];
    const float* as2 = (const float*)d_in[12];
    const float* ad2 = (const float*)d_in[13];
    const float* ae2 = (const float*)d_in[14];
    const float* b2  = (const float*)d_in[15];
    const float* Wl  = (const float*)d_in[16];
    const float* bl  = (const float*)d_in[17];
    float* out = (float*)d_out;

    const int* srcp = eidx;
    const int* dstp = eidx + EE;

    __half* hhbuf; cudaGetSymbolAddress((void**)&hhbuf, d_hh);
    float*  obuf;  cudaGetSymbolAddress((void**)&obuf, d_o);
    float*  ea1b;  cudaGetSymbolAddress((void**)&ea1b, d_ea1);
    float*  ea2b;  cudaGetSymbolAddress((void**)&ea2b, d_ea2);

    // ---- CSR build + per-edge scalars ----
    init_k<<<(NN + 255) / 256, 256>>>(We1, ae1, We2, ae2);
    hist_k<<<(EE + 255) / 256, 256>>>(dstp);
    scan1_k<<<NBLK, 256>>>();
    scan2_k<<<1, 256>>>();
    scan3_k<<<NBLK, 256>>>();
    scatter_k<<<(EE + 255) / 256, 256>>>(srcp, dstp, edge_attr);

    const int warps_grid = (NN * 32 + 255) / 256;

    // ---- layer 1 ----
    gemm_fused_k<<<(NN + 127) / 128, 256>>>(x, W1, as1, ad1, hhbuf, NN, FF);
    attn_agg_k<false><<<warps_grid, 256>>>(ea1b, b1, obuf, batch);

    // ---- layer 2 (pool fused into aggregation) ----
    gemm_fused_k<<<(NN + 127) / 128, 256>>>(obuf, W2, as2, ad2, hhbuf, NN, HH);
    attn_agg_k<true><<<warps_grid, 256>>>(ea2b, b2, nullptr, batch);

    // ---- head ----
    head_k<<<GG, 32>>>(Wl, bl, out);
}

// round 5
// speedup vs baseline: 1.5426x; 1.5424x over previous
#include <cuda_runtime.h>
#include <cuda_fp16.h>
#include <math.h>
#include <stdint.h>

// Problem constants
#define NN 50000
#define EE 800000
#define FF 86
#define HH 128
#define EDD 16
#define CC 18
#define GG 64
#define NEG_SLOPE 0.2f

#define NBLK ((NN + 255) / 256)   // 196 scan blocks

// ---------------- scratch (static device globals; no allocation) ----------------
__device__ int    d_deg[NN];
__device__ int    d_cur[NN];
__device__ int    d_off[NN + 1];
__device__ int    d_bsum[256];
__device__ int    d_srcs[EE];
__device__ float  d_ea1[EE];
__device__ float  d_ea2[EE];
__device__ float  d_aw[EE];
__device__ __half d_hh[(size_t)NN * HH];  // fp16 transformed features (gather source)
__device__ float  d_o[(size_t)NN * HH];   // layer output (fp32, gemm input)
__device__ float  d_hs[NN];
__device__ float  d_hd[NN];
__device__ float  d_v1[EDD];
__device__ float  d_v2[EDD];
__device__ float  d_pool[GG * HH];

// ---------------- small helpers ----------------
__device__ __forceinline__ float to_tf32(float x) {
    uint32_t u;
    asm("cvt.rna.tf32.f32 %0, %1;" : "=r"(u) : "f"(x));
    return __uint_as_float(u);
}

__device__ __forceinline__ int warp_iscan(int x, int lane) {
#pragma unroll
    for (int o = 1; o < 32; o <<= 1) {
        int y = __shfl_up_sync(0xffffffffu, x, o);
        if (lane >= o) x += y;
    }
    return x;
}

// ---------------- kernels ----------------

// zero counters/pool + precompute v1 = We1@ae1, v2 = We2@ae2 (warp-parallel dots)
__global__ void init_k(const float* __restrict__ We1, const float* __restrict__ ae1,
                       const float* __restrict__ We2, const float* __restrict__ ae2) {
    int i = blockIdx.x * blockDim.x + threadIdx.x;
    if (i < NN) { d_deg[i] = 0; d_cur[i] = 0; }
    if (i < GG * HH) d_pool[i] = 0.0f;
    if (blockIdx.x == 0) {
        int warp = threadIdx.x >> 5, lane = threadIdx.x & 31;
        for (int o = warp; o < 2 * EDD; o += 8) {   // 32 dot products, 8 warps
            int t = o & (EDD - 1);
            const float* W  = (o < EDD) ? We1 : We2;
            const float* ae = (o < EDD) ? ae1 : ae2;
            float s = 0.f;
            for (int h = lane; h < HH; h += 32) s += W[t * HH + h] * ae[h];
#pragma unroll
            for (int q = 16; q; q >>= 1) s += __shfl_xor_sync(0xffffffffu, s, q);
            if (lane == 0) ((o < EDD) ? d_v1 : d_v2)[t] = s;
        }
    }
}

__global__ void hist_k(const int* __restrict__ dst) {
    int e = blockIdx.x * blockDim.x + threadIdx.x;
    if (e < EE) atomicAdd(&d_deg[dst[e]], 1);
}

// ---- 3-phase multi-block exclusive scan of d_deg -> d_off ----
__global__ void scan1_k() {
    __shared__ int ws[8];
    int t = threadIdx.x, lane = t & 31, warp = t >> 5;
    int i = blockIdx.x * 256 + t;
    int v = (i < NN) ? d_deg[i] : 0;
    int wi = warp_iscan(v, lane);
    if (lane == 31) ws[warp] = wi;
    __syncthreads();
    if (warp == 0) {
        int s = (lane < 8) ? ws[lane] : 0;
        int si = warp_iscan(s, lane);
        if (lane < 8) ws[lane] = si - s;  // exclusive
    }
    __syncthreads();
    int excl = ws[warp] + wi - v;
    if (i < NN) d_off[i] = excl;
    if (t == 255) d_bsum[blockIdx.x] = ws[7] + wi;  // block total
}

__global__ void scan2_k() {
    __shared__ int ws[8];
    int t = threadIdx.x, lane = t & 31, warp = t >> 5;
    int v = (t < NBLK) ? d_bsum[t] : 0;
    int wi = warp_iscan(v, lane);
    if (lane == 31) ws[warp] = wi;
    __syncthreads();
    if (warp == 0) {
        int s = (lane < 8) ? ws[lane] : 0;
        int si = warp_iscan(s, lane);
        if (lane < 8) ws[lane] = si - s;
    }
    __syncthreads();
    int incl = ws[warp] + wi;
    if (t < NBLK) d_bsum[t] = incl - v;   // exclusive
    if (t == NBLK - 1) d_off[NN] = incl;  // grand total (== EE)
}

__global__ void scan3_k() {
    int i = blockIdx.x * 256 + threadIdx.x;
    if (i < NN) d_off[i] += d_bsum[blockIdx.x];
}

// scatter edges into CSR-by-dst; also compute per-edge scalars for both layers
__global__ void scatter_k(const int* __restrict__ src, const int* __restrict__ dst,
                          const float* __restrict__ edge_attr) {
    int e = blockIdx.x * blockDim.x + threadIdx.x;
    if (e >= EE) return;
    int d = dst[e];
    int p = d_off[d] + atomicAdd(&d_cur[d], 1);
    d_srcs[p] = src[e];
    const float4* ea = (const float4*)(edge_attr + (size_t)e * EDD);
    float s1 = 0.f, s2 = 0.f;
#pragma unroll
    for (int q = 0; q < 4; q++) {
        float4 xv = ea[q];
        s1 += xv.x * d_v1[q * 4 + 0] + xv.y * d_v1[q * 4 + 1]
            + xv.z * d_v1[q * 4 + 2] + xv.w * d_v1[q * 4 + 3];
        s2 += xv.x * d_v2[q * 4 + 0] + xv.y * d_v2[q * 4 + 1]
            + xv.z * d_v2[q * 4 + 2] + xv.w * d_v2[q * 4 + 3];
    }
    d_ea1[p] = s1;
    d_ea2[p] = s2;
}

// ---------------- tf32 GEMM + fused epilogue (NO atomics) ----------------
// hh[M,128](fp16) = A[M,K] @ B[K,128]; hs = hh@a_src; hd = hh@a_dst (fp32 from accs)
// block tile 128x128, K chunked by 32; 8 warps, warp tile 64x32 (m16n8k8 atoms)
#define KC 32
__global__ __launch_bounds__(256) void gemm_fused_k(const float* __restrict__ A,
                                                    const float* __restrict__ B,
                                                    const float* __restrict__ a_src,
                                                    const float* __restrict__ a_dst,
                                                    __half* __restrict__ Chh,
                                                    int M, int K) {
    __shared__ float As[128][KC + 4];    // stride 36
    __shared__ float Bs[KC][HH + 4];     // stride 132
    __shared__ float hs_part[4][128], hd_part[4][128];
    int tid = threadIdx.x;
    int wid = tid >> 5, lane = tid & 31;
    int mw = wid >> 2, nw = wid & 3;          // 2 x 4 warp grid
    int gp = lane >> 2, t4 = lane & 3;        // fragment coords
    int rowBase = blockIdx.x * 128;

    float acc[4][4][4];
#pragma unroll
    for (int a = 0; a < 4; a++)
#pragma unroll
        for (int b = 0; b < 4; b++)
#pragma unroll
            for (int c = 0; c < 4; c++) acc[a][b][c] = 0.f;

    int nChunks = (K + KC - 1) / KC;
    for (int kc = 0; kc < nChunks; kc++) {
        int kbase = kc * KC;
        {
            int rl = tid >> 3;   // 0..31
            int kl = tid & 7;    // 0..7
#pragma unroll
            for (int i = 0; i < 4; i++) {
                int r = rl + i * 32;
                int grow = rowBase + r;
                const float* arow = A + (size_t)grow * K;
#pragma unroll
                for (int j = 0; j < 4; j++) {
                    int k = kl + j * 8;
                    int gk = kbase + k;
                    float v = (grow < M && gk < K) ? arow[gk] : 0.f;
                    As[r][k] = to_tf32(v);
                }
            }
        }
        {
#pragma unroll
            for (int i = 0; i < 4; i++) {
                int idx = tid + 256 * i;
                int k = idx >> 5, f4 = idx & 31;
                int gk = kbase + k;
                float4 bv = make_float4(0.f, 0.f, 0.f, 0.f);
                if (gk < K) bv = *(const float4*)&B[(size_t)gk * HH + f4 * 4];
                Bs[k][f4 * 4 + 0] = to_tf32(bv.x);
                Bs[k][f4 * 4 + 1] = to_tf32(bv.y);
                Bs[k][f4 * 4 + 2] = to_tf32(bv.z);
                Bs[k][f4 * 4 + 3] = to_tf32(bv.w);
            }
        }
        __syncthreads();
#pragma unroll
        for (int ka = 0; ka < 4; ka++) {
            int kb = ka * 8;
            uint32_t af[4][4];
#pragma unroll
            for (int mi = 0; mi < 4; mi++) {
                int r0 = mw * 64 + mi * 16 + gp;
                af[mi][0] = __float_as_uint(As[r0][kb + t4]);
                af[mi][1] = __float_as_uint(As[r0 + 8][kb + t4]);
                af[mi][2] = __float_as_uint(As[r0][kb + t4 + 4]);
                af[mi][3] = __float_as_uint(As[r0 + 8][kb + t4 + 4]);
            }
            uint32_t bf[4][2];
#pragma unroll
            for (int ni = 0; ni < 4; ni++) {
                int c0 = nw * 32 + ni * 8 + gp;
                bf[ni][0] = __float_as_uint(Bs[kb + t4][c0]);
                bf[ni][1] = __float_as_uint(Bs[kb + t4 + 4][c0]);
            }
#pragma unroll
            for (int mi = 0; mi < 4; mi++)
#pragma unroll
                for (int ni = 0; ni < 4; ni++) {
                    asm volatile(
                        "mma.sync.aligned.m16n8k8.row.col.f32.tf32.tf32.f32 "
                        "{%0,%1,%2,%3}, {%4,%5,%6,%7}, {%8,%9}, {%0,%1,%2,%3};"
                        : "+f"(acc[mi][ni][0]), "+f"(acc[mi][ni][1]),
                          "+f"(acc[mi][ni][2]), "+f"(acc[mi][ni][3])
                        : "r"(af[mi][0]), "r"(af[mi][1]), "r"(af[mi][2]), "r"(af[mi][3]),
                          "r"(bf[ni][0]), "r"(bf[ni][1]));
                }
        }
        __syncthreads();
    }

    // epilogue: write fp16 C; hs/hd via quad-shuffle + smem partials (no atomics)
    float avs[8], avd[8];
#pragma unroll
    for (int ni = 0; ni < 4; ni++) {
        int c = nw * 32 + ni * 8 + 2 * t4;
        avs[ni * 2]     = __ldg(&a_src[c]);
        avs[ni * 2 + 1] = __ldg(&a_src[c + 1]);
        avd[ni * 2]     = __ldg(&a_dst[c]);
        avd[ni * 2 + 1] = __ldg(&a_dst[c + 1]);
    }
#pragma unroll
    for (int mi = 0; mi < 4; mi++) {
#pragma unroll
        for (int hf = 0; hf < 2; hf++) {
            int rl = mw * 64 + mi * 16 + gp + 8 * hf;
            int r = rowBase + rl;
            float ss = 0.f, dd = 0.f;
#pragma unroll
            for (int ni = 0; ni < 4; ni++) {
                int c = nw * 32 + ni * 8 + 2 * t4;
                float v0 = acc[mi][ni][2 * hf + 0];
                float v1 = acc[mi][ni][2 * hf + 1];
                ss += v0 * avs[ni * 2] + v1 * avs[ni * 2 + 1];
                dd += v0 * avd[ni * 2] + v1 * avd[ni * 2 + 1];
                if (r < M)
                    *(__half2*)&Chh[(size_t)r * HH + c] =
                        __floats2half2_rn(v0, v1);
            }
            // quad lanes (t4=0..3) share row rl: fold within quad
            ss += __shfl_xor_sync(0xffffffffu, ss, 1);
            ss += __shfl_xor_sync(0xffffffffu, ss, 2);
            dd += __shfl_xor_sync(0xffffffffu, dd, 1);
            dd += __shfl_xor_sync(0xffffffffu, dd, 2);
            if (t4 == 0) { hs_part[nw][rl] = ss; hd_part[nw][rl] = dd; }
        }
    }
    __syncthreads();
    if (tid < 128) {
        int r = rowBase + tid;
        if (r < M) {
            d_hs[r] = hs_part[0][tid] + hs_part[1][tid] + hs_part[2][tid] + hs_part[3][tid];
            d_hd[r] = hd_part[0][tid] + hd_part[1][tid] + hd_part[2][tid] + hd_part[3][tid];
        }
    }
}

// one warp per dst node: logits -> segment softmax -> weighted fp16 gather
// out[n,:] = relu(sum + bias)
__global__ void attn_agg_k(const float* __restrict__ ea, const float* __restrict__ bias,
                           float* __restrict__ out) {
    int gt = blockIdx.x * blockDim.x + threadIdx.x;
    int n = gt >> 5, lane = gt & 31;
    if (n >= NN) return;
    int b0 = d_off[n], b1 = d_off[n + 1];
    float hdn = d_hd[n];

    float lm = -1e30f;
    for (int j = b0 + lane; j < b1; j += 32) {
        float a = d_hs[d_srcs[j]] + hdn + ea[j];
        a = (a > 0.f) ? a : NEG_SLOPE * a;
        d_aw[j] = a;
        lm = fmaxf(lm, a);
    }
#pragma unroll
    for (int o = 16; o; o >>= 1) lm = fmaxf(lm, __shfl_xor_sync(0xffffffffu, lm, o));

    float ls = 0.f;
    for (int j = b0 + lane; j < b1; j += 32) {
        float ex = __expf(d_aw[j] - lm);
        d_aw[j] = ex;
        ls += ex;
    }
#pragma unroll
    for (int o = 16; o; o >>= 1) ls += __shfl_xor_sync(0xffffffffu, ls, o);
    float inv = 1.f / fmaxf(ls, 1e-16f);

    __syncwarp();

    // weighted gather: lane handles 4 contiguous features (8 bytes fp16)
    float4 acc = make_float4(0.f, 0.f, 0.f, 0.f);
    int fo = lane << 2;
#pragma unroll 4
    for (int j = b0; j < b1; j++) {
        float w = d_aw[j] * inv;
        int s = d_srcs[j];
        uint2 raw = *(const uint2*)(d_hh + (size_t)s * HH + fo);
        float2 f0 = __half22float2(*(__half2*)&raw.x);
        float2 f1 = __half22float2(*(__half2*)&raw.y);
        acc.x += w * f0.x; acc.y += w * f0.y; acc.z += w * f1.x; acc.w += w * f1.y;
    }
    float4 bv = *(const float4*)(bias + fo);
    float4 o4;
    o4.x = fmaxf(acc.x + bv.x, 0.f);
    o4.y = fmaxf(acc.y + bv.y, 0.f);
    o4.z = fmaxf(acc.z + bv.z, 0.f);
    o4.w = fmaxf(acc.w + bv.w, 0.f);
    *(float4*)(out + (size_t)n * HH + fo) = o4;
}

// global max pool over sorted batch segments (values >= 0 after relu, pool pre-zeroed)
#define NPB 256
__global__ void pool_k(const float* __restrict__ o, const int* __restrict__ batch) {
    int f = threadIdx.x;  // 128
    int n0 = blockIdx.x * NPB;
    int n1 = min(n0 + NPB, NN);
    if (n0 >= NN) return;
    int cur = batch[n0];
    float lm = 0.f;
    for (int n = n0; n < n1; n++) {
        int g = batch[n];
        if (g != cur) {
            atomicMax((int*)&d_pool[cur * HH + f], __float_as_int(lm));
            cur = g;
            lm = 0.f;
        }
        lm = fmaxf(lm, o[(size_t)n * HH + f]);
    }
    atomicMax((int*)&d_pool[cur * HH + f], __float_as_int(lm));
}

// classifier + log_softmax: one warp per graph
__global__ void head_k(const float* __restrict__ Wl, const float* __restrict__ bl,
                       float* __restrict__ out) {
    int g = blockIdx.x;
    int lane = threadIdx.x;
    float logit = -INFINITY;
    if (lane < CC) {
        float s = bl[lane];
        const float* pr = d_pool + g * HH;
        for (int k = 0; k < HH; k++) s += pr[k] * Wl[k * CC + lane];
        logit = s;
    }
    float m = logit;
#pragma unroll
    for (int o = 16; o; o >>= 1) m = fmaxf(m, __shfl_xor_sync(0xffffffffu, m, o));
    float e = (lane < CC) ? __expf(logit - m) : 0.f;
    float se = e;
#pragma unroll
    for (int o = 16; o; o >>= 1) se += __shfl_xor_sync(0xffffffffu, se, o);
    float lse = m + logf(se);
    if (lane < CC) out[g * CC + lane] = logit - lse;
}

// ---------------- launch ----------------
extern "C" void kernel_launch(void* const* d_in, const int* in_sizes, int n_in,
                              void* d_out, int out_size) {
    const float* x         = (const float*)d_in[0];
    const int*   eidx      = (const int*)d_in[1];
    const float* edge_attr = (const float*)d_in[2];
    const int*   batch     = (const int*)d_in[3];
    const float* W1  = (const float*)d_in[4];
    const float* We1 = (const float*)d_in[5];
    const float* as1 = (const float*)d_in[6];
    const float* ad1 = (const float*)d_in[7];
    const float* ae1 = (const float*)d_in[8];
    const float* b1  = (const float*)d_in[9];
    const float* W2  = (const float*)d_in[10];
    const float* We2 = (const float*)d_in[11];
    const float* as2 = (const float*)d_in[12];
    const float* ad2 = (const float*)d_in[13];
    const float* ae2 = (const float*)d_in[14];
    const float* b2  = (const float*)d_in[15];
    const float* Wl  = (const float*)d_in[16];
    const float* bl  = (const float*)d_in[17];
    float* out = (float*)d_out;

    const int* srcp = eidx;
    const int* dstp = eidx + EE;

    __half* hhbuf; cudaGetSymbolAddress((void**)&hhbuf, d_hh);
    float*  obuf;  cudaGetSymbolAddress((void**)&obuf, d_o);
    float*  ea1b;  cudaGetSymbolAddress((void**)&ea1b, d_ea1);
    float*  ea2b;  cudaGetSymbolAddress((void**)&ea2b, d_ea2);

    // ---- CSR build + per-edge scalars ----
    init_k<<<(NN + 255) / 256, 256>>>(We1, ae1, We2, ae2);
    hist_k<<<(EE + 255) / 256, 256>>>(dstp);
    scan1_k<<<NBLK, 256>>>();
    scan2_k<<<1, 256>>>();
    scan3_k<<<NBLK, 256>>>();
    scatter_k<<<(EE + 255) / 256, 256>>>(srcp, dstp, edge_attr);

    const int warps_grid = (NN * 32 + 255) / 256;

    // ---- layer 1 ----
    gemm_fused_k<<<(NN + 127) / 128, 256>>>(x, W1, as1, ad1, hhbuf, NN, FF);
    attn_agg_k<<<warps_grid, 256>>>(ea1b, b1, obuf);

    // ---- layer 2 ----
    gemm_fused_k<<<(NN + 127) / 128, 256>>>(obuf, W2, as2, ad2, hhbuf, NN, HH);
    attn_agg_k<<<warps_grid, 256>>>(ea2b, b2, obuf);

    // ---- pool + head ----
    pool_k<<<(NN + NPB - 1) / NPB, 128>>>(obuf, batch);
    head_k<<<GG, 32>>>(Wl, bl, out);
}

// round 7
// speedup vs baseline: 1.5654x; 1.0148x over previous
#include <cuda_runtime.h>
#include <cuda_fp16.h>
#include <math.h>
#include <stdint.h>

// Problem constants
#define NN 50000
#define EE 800000
#define FF 86
#define HH 128
#define EDD 16
#define CC 18
#define GG 64
#define NEG_SLOPE 0.2f

#define NBLK ((NN + 255) / 256)   // 196 scan blocks

// ---------------- scratch (static device globals; no allocation) ----------------
__device__ int    d_deg[NN];
__device__ int    d_cur[NN];
__device__ int    d_off[NN + 1];
__device__ int    d_bsum[256];
__device__ int    d_srcs[EE];
__device__ float2 d_ea12[EE];             // per-edge scalars for layer1 (.x) / layer2 (.y)
__device__ float  d_aw[EE];
__device__ __half d_hh[(size_t)NN * HH];  // fp16 transformed features (gather source)
__device__ float  d_o[(size_t)NN * HH];   // layer output (fp32, gemm input)
__device__ float  d_hs[NN];
__device__ float  d_hd[NN];
__device__ float  d_v1[EDD];
__device__ float  d_v2[EDD];
__device__ float  d_pool[GG * HH];

// ---------------- small helpers ----------------
__device__ __forceinline__ float to_tf32(float x) {
    uint32_t u;
    asm("cvt.rna.tf32.f32 %0, %1;" : "=r"(u) : "f"(x));
    return __uint_as_float(u);
}

__device__ __forceinline__ int warp_iscan(int x, int lane) {
#pragma unroll
    for (int o = 1; o < 32; o <<= 1) {
        int y = __shfl_up_sync(0xffffffffu, x, o);
        if (lane >= o) x += y;
    }
    return x;
}

// ---------------- kernels ----------------

// zero counters/pool + precompute v1 = We1@ae1, v2 = We2@ae2 (warp-parallel dots)
__global__ void init_k(const float* __restrict__ We1, const float* __restrict__ ae1,
                       const float* __restrict__ We2, const float* __restrict__ ae2) {
    int i = blockIdx.x * blockDim.x + threadIdx.x;
    if (i < NN) { d_deg[i] = 0; d_cur[i] = 0; }
    if (i < GG * HH) d_pool[i] = 0.0f;
    if (blockIdx.x == 0) {
        int warp = threadIdx.x >> 5, lane = threadIdx.x & 31;
        for (int o = warp; o < 2 * EDD; o += 8) {   // 32 dot products, 8 warps
            int t = o & (EDD - 1);
            const float* W  = (o < EDD) ? We1 : We2;
            const float* ae = (o < EDD) ? ae1 : ae2;
            float s = 0.f;
            for (int h = lane; h < HH; h += 32) s += W[t * HH + h] * ae[h];
#pragma unroll
            for (int q = 16; q; q >>= 1) s += __shfl_xor_sync(0xffffffffu, s, q);
            if (lane == 0) ((o < EDD) ? d_v1 : d_v2)[t] = s;
        }
    }
}

__global__ void hist_k(const int* __restrict__ dst) {
    int e = blockIdx.x * blockDim.x + threadIdx.x;
    if (e < EE) atomicAdd(&d_deg[dst[e]], 1);
}

// ---- scan phase 1: block-local exclusive scan, block totals to d_bsum ----
__global__ void scan1_k() {
    __shared__ int ws[8];
    int t = threadIdx.x, lane = t & 31, warp = t >> 5;
    int i = blockIdx.x * 256 + t;
    int v = (i < NN) ? d_deg[i] : 0;
    int wi = warp_iscan(v, lane);
    if (lane == 31) ws[warp] = wi;
    __syncthreads();
    if (warp == 0) {
        int s = (lane < 8) ? ws[lane] : 0;
        int si = warp_iscan(s, lane);
        if (lane < 8) ws[lane] = si - s;  // exclusive
    }
    __syncthreads();
    int excl = ws[warp] + wi - v;
    if (i < NN) d_off[i] = excl;
    if (t == 255) d_bsum[blockIdx.x] = ws[7] + wi;  // block total
}

// ---- scan phase 2 (merged): each block sums its prefix of d_bsum itself ----
__global__ void scan3_k() {
    __shared__ int red[8];
    __shared__ int pre_s;
    int t = threadIdx.x, lane = t & 31, warp = t >> 5;
    int v = (t < blockIdx.x) ? d_bsum[t] : 0;   // blockIdx.x <= NBLK-1 <= 255
#pragma unroll
    for (int o = 16; o; o >>= 1) v += __shfl_xor_sync(0xffffffffu, v, o);
    if (lane == 0) red[warp] = v;
    __syncthreads();
    if (t == 0) {
        int s = 0;
#pragma unroll
        for (int q = 0; q < 8; q++) s += red[q];
        pre_s = s;
    }
    __syncthreads();
    int i = blockIdx.x * 256 + t;
    if (i < NN) d_off[i] += pre_s;
    if (i == 0) d_off[NN] = EE;
}

// scatter edges into CSR-by-dst; also compute per-edge scalars for both layers
__global__ void scatter_k(const int* __restrict__ src, const int* __restrict__ dst,
                          const float* __restrict__ edge_attr) {
    int e = blockIdx.x * blockDim.x + threadIdx.x;
    if (e >= EE) return;
    int d = dst[e];
    int p = d_off[d] + atomicAdd(&d_cur[d], 1);
    d_srcs[p] = src[e];
    const float4* ea = (const float4*)(edge_attr + (size_t)e * EDD);
    float s1 = 0.f, s2 = 0.f;
#pragma unroll
    for (int q = 0; q < 4; q++) {
        float4 xv = ea[q];
        s1 += xv.x * d_v1[q * 4 + 0] + xv.y * d_v1[q * 4 + 1]
            + xv.z * d_v1[q * 4 + 2] + xv.w * d_v1[q * 4 + 3];
        s2 += xv.x * d_v2[q * 4 + 0] + xv.y * d_v2[q * 4 + 1]
            + xv.z * d_v2[q * 4 + 2] + xv.w * d_v2[q * 4 + 3];
    }
    d_ea12[p] = make_float2(s1, s2);
}

// ---------------- tf32 GEMM (pipelined) + fused epilogue ----------------
// hh[M,128](fp16) = A[M,K] @ B[K,128]; hs = hh@a_src; hd = hh@a_dst (fp32 from accs)
// block tile 128x128, K chunked by 32; 8 warps, warp tile 64x32 (m16n8k8 atoms).
// Register-staged prefetch: LDG for chunk k+1 issued before chunk k's MMAs.
#define KC 32
__global__ __launch_bounds__(256) void gemm_fused_k(const float* __restrict__ A,
                                                    const float* __restrict__ B,
                                                    const float* __restrict__ a_src,
                                                    const float* __restrict__ a_dst,
                                                    __half* __restrict__ Chh,
                                                    int M, int K) {
    __shared__ float As[128][KC + 4];    // stride 36
    __shared__ float Bs[KC][HH + 4];     // stride 132
    __shared__ float hs_part[4][128], hd_part[4][128];
    int tid = threadIdx.x;
    int wid = tid >> 5, lane = tid & 31;
    int mw = wid >> 2, nw = wid & 3;          // 2 x 4 warp grid
    int gp = lane >> 2, t4 = lane & 3;        // fragment coords
    int rowBase = blockIdx.x * 128;

    int rl = tid >> 3;   // 0..31 (A row group)
    int kl = tid & 7;    // 0..7  (A col group)
    float  aR[16];
    float4 bR[4];

    auto loadA = [&](int kbase) {
#pragma unroll
        for (int i = 0; i < 4; i++) {
            int grow = rowBase + rl + i * 32;
            const float* arow = A + (size_t)grow * K;
#pragma unroll
            for (int j = 0; j < 4; j++) {
                int gk = kbase + kl + j * 8;
                aR[i * 4 + j] = (grow < M && gk < K) ? arow[gk] : 0.f;
            }
        }
    };
    auto loadB = [&](int kbase) {
#pragma unroll
        for (int i = 0; i < 4; i++) {
            int idx = tid + 256 * i;
            int k = idx >> 5, f4 = idx & 31;
            int gk = kbase + k;
            bR[i] = (gk < K) ? *(const float4*)&B[(size_t)gk * HH + f4 * 4]
                             : make_float4(0.f, 0.f, 0.f, 0.f);
        }
    };
    auto stsAB = [&]() {
#pragma unroll
        for (int i = 0; i < 4; i++)
#pragma unroll
            for (int j = 0; j < 4; j++)
                As[rl + i * 32][kl + j * 8] = to_tf32(aR[i * 4 + j]);
#pragma unroll
        for (int i = 0; i < 4; i++) {
            int idx = tid + 256 * i;
            int k = idx >> 5, f4 = idx & 31;
            Bs[k][f4 * 4 + 0] = to_tf32(bR[i].x);
            Bs[k][f4 * 4 + 1] = to_tf32(bR[i].y);
            Bs[k][f4 * 4 + 2] = to_tf32(bR[i].z);
            Bs[k][f4 * 4 + 3] = to_tf32(bR[i].w);
        }
    };

    float acc[4][4][4];
#pragma unroll
    for (int a = 0; a < 4; a++)
#pragma unroll
        for (int b = 0; b < 4; b++)
#pragma unroll
            for (int c = 0; c < 4; c++) acc[a][b][c] = 0.f;

    int nChunks = (K + KC - 1) / KC;
    loadA(0); loadB(0); stsAB();
    __syncthreads();

    for (int kc = 0; kc < nChunks; kc++) {
        bool more = (kc + 1) < nChunks;
        if (more) { loadA((kc + 1) * KC); loadB((kc + 1) * KC); }  // in-flight during MMA
#pragma unroll
        for (int ka = 0; ka < 4; ka++) {
            int kb = ka * 8;
            uint32_t af[4][4];
#pragma unroll
            for (int mi = 0; mi < 4; mi++) {
                int r0 = mw * 64 + mi * 16 + gp;
                af[mi][0] = __float_as_uint(As[r0][kb + t4]);
                af[mi][1] = __float_as_uint(As[r0 + 8][kb + t4]);
                af[mi][2] = __float_as_uint(As[r0][kb + t4 + 4]);
                af[mi][3] = __float_as_uint(As[r0 + 8][kb + t4 + 4]);
            }
            uint32_t bf[4][2];
#pragma unroll
            for (int ni = 0; ni < 4; ni++) {
                int c0 = nw * 32 + ni * 8 + gp;
                bf[ni][0] = __float_as_uint(Bs[kb + t4][c0]);
                bf[ni][1] = __float_as_uint(Bs[kb + t4 + 4][c0]);
            }
#pragma unroll
            for (int mi = 0; mi < 4; mi++)
#pragma unroll
                for (int ni = 0; ni < 4; ni++) {
                    asm volatile(
                        "mma.sync.aligned.m16n8k8.row.col.f32.tf32.tf32.f32 "
                        "{%0,%1,%2,%3}, {%4,%5,%6,%7}, {%8,%9}, {%0,%1,%2,%3};"
                        : "+f"(acc[mi][ni][0]), "+f"(acc[mi][ni][1]),
                          "+f"(acc[mi][ni][2]), "+f"(acc[mi][ni][3])
                        : "r"(af[mi][0]), "r"(af[mi][1]), "r"(af[mi][2]), "r"(af[mi][3]),
                          "r"(bf[ni][0]), "r"(bf[ni][1]));
                }
        }
        __syncthreads();
        if (more) { stsAB(); __syncthreads(); }
    }

    // epilogue: write fp16 C; hs/hd via quad-shuffle + smem partials (no atomics)
    float avs[8], avd[8];
#pragma unroll
    for (int ni = 0; ni < 4; ni++) {
        int c = nw * 32 + ni * 8 + 2 * t4;
        avs[ni * 2]     = __ldg(&a_src[c]);
        avs[ni * 2 + 1] = __ldg(&a_src[c + 1]);
        avd[ni * 2]     = __ldg(&a_dst[c]);
        avd[ni * 2 + 1] = __ldg(&a_dst[c + 1]);
    }
#pragma unroll
    for (int mi = 0; mi < 4; mi++) {
#pragma unroll
        for (int hf = 0; hf < 2; hf++) {
            int rl2 = mw * 64 + mi * 16 + gp + 8 * hf;
            int r = rowBase + rl2;
            float ss = 0.f, dd = 0.f;
#pragma unroll
            for (int ni = 0; ni < 4; ni++) {
                int c = nw * 32 + ni * 8 + 2 * t4;
                float v0 = acc[mi][ni][2 * hf + 0];
                float v1 = acc[mi][ni][2 * hf + 1];
                ss += v0 * avs[ni * 2] + v1 * avs[ni * 2 + 1];
                dd += v0 * avd[ni * 2] + v1 * avd[ni * 2 + 1];
                if (r < M)
                    *(__half2*)&Chh[(size_t)r * HH + c] =
                        __floats2half2_rn(v0, v1);
            }
            // quad lanes (t4=0..3) share row rl2: fold within quad
            ss += __shfl_xor_sync(0xffffffffu, ss, 1);
            ss += __shfl_xor_sync(0xffffffffu, ss, 2);
            dd += __shfl_xor_sync(0xffffffffu, dd, 1);
            dd += __shfl_xor_sync(0xffffffffu, dd, 2);
            if (t4 == 0) { hs_part[nw][rl2] = ss; hd_part[nw][rl2] = dd; }
        }
    }
    __syncthreads();
    if (tid < 128) {
        int r = rowBase + tid;
        if (r < M) {
            d_hs[r] = hs_part[0][tid] + hs_part[1][tid] + hs_part[2][tid] + hs_part[3][tid];
            d_hd[r] = hd_part[0][tid] + hd_part[1][tid] + hd_part[2][tid] + hd_part[3][tid];
        }
    }
}

// one warp per dst node: logits -> segment softmax (shift-free: |alpha| bounded,
// softmax shift-invariant) -> weighted fp16 gather.  out[n,:] = relu(sum + bias)
__global__ void attn_agg_k(const float* __restrict__ bias, float* __restrict__ out,
                           int sel) {
    int gt = blockIdx.x * blockDim.x + threadIdx.x;
    int n = gt >> 5, lane = gt & 31;
    if (n >= NN) return;
    int b0 = d_off[n], b1 = d_off[n + 1];
    float hdn = d_hd[n];

    float ls = 0.f;
    for (int j = b0 + lane; j < b1; j += 32) {
        float2 e2 = d_ea12[j];
        float a = d_hs[d_srcs[j]] + hdn + (sel ? e2.y : e2.x);
        a = (a > 0.f) ? a : NEG_SLOPE * a;
        float ex = __expf(a);
        d_aw[j] = ex;
        ls += ex;
    }
#pragma unroll
    for (int o = 16; o; o >>= 1) ls += __shfl_xor_sync(0xffffffffu, ls, o);
    float inv = 1.f / fmaxf(ls, 1e-16f);

    __syncwarp();

    // weighted gather: lane handles 4 contiguous features (8 bytes fp16)
    float4 acc = make_float4(0.f, 0.f, 0.f, 0.f);
    int fo = lane << 2;
#pragma unroll 4
    for (int j = b0; j < b1; j++) {
        float w = d_aw[j] * inv;
        int s = d_srcs[j];
        uint2 raw = *(const uint2*)(d_hh + (size_t)s * HH + fo);
        float2 f0 = __half22float2(*(__half2*)&raw.x);
        float2 f1 = __half22float2(*(__half2*)&raw.y);
        acc.x += w * f0.x; acc.y += w * f0.y; acc.z += w * f1.x; acc.w += w * f1.y;
    }
    float4 bv = *(const float4*)(bias + fo);
    float4 o4;
    o4.x = fmaxf(acc.x + bv.x, 0.f);
    o4.y = fmaxf(acc.y + bv.y, 0.f);
    o4.z = fmaxf(acc.z + bv.z, 0.f);
    o4.w = fmaxf(acc.w + bv.w, 0.f);
    *(float4*)(out + (size_t)n * HH + fo) = o4;
}

// global max pool over sorted batch segments (values >= 0 after relu, pool pre-zeroed)
#define NPB 256
__global__ void pool_k(const float* __restrict__ o, const int* __restrict__ batch) {
    int f = threadIdx.x;  // 128
    int n0 = blockIdx.x * NPB;
    int n1 = min(n0 + NPB, NN);
    if (n0 >= NN) return;
    int cur = batch[n0];
    float lm = 0.f;
    for (int n = n0; n < n1; n++) {
        int g = batch[n];
        if (g != cur) {
            atomicMax((int*)&d_pool[cur * HH + f], __float_as_int(lm));
            cur = g;
            lm = 0.f;
        }
        lm = fmaxf(lm, o[(size_t)n * HH + f]);
    }
    atomicMax((int*)&d_pool[cur * HH + f], __float_as_int(lm));
}

// classifier + log_softmax: one warp per graph
__global__ void head_k(const float* __restrict__ Wl, const float* __restrict__ bl,
                       float* __restrict__ out) {
    int g = blockIdx.x;
    int lane = threadIdx.x;
    float logit = -INFINITY;
    if (lane < CC) {
        float s = bl[lane];
        const float* pr = d_pool + g * HH;
        for (int k = 0; k < HH; k++) s += pr[k] * Wl[k * CC + lane];
        logit = s;
    }
    float m = logit;
#pragma unroll
    for (int o = 16; o; o >>= 1) m = fmaxf(m, __shfl_xor_sync(0xffffffffu, m, o));
    float e = (lane < CC) ? __expf(logit - m) : 0.f;
    float se = e;
#pragma unroll
    for (int o = 16; o; o >>= 1) se += __shfl_xor_sync(0xffffffffu, se, o);
    float lse = m + logf(se);
    if (lane < CC) out[g * CC + lane] = logit - lse;
}

// ---------------- launch ----------------
extern "C" void kernel_launch(void* const* d_in, const int* in_sizes, int n_in,
                              void* d_out, int out_size) {
    const float* x         = (const float*)d_in[0];
    const int*   eidx      = (const int*)d_in[1];
    const float* edge_attr = (const float*)d_in[2];
    const int*   batch     = (const int*)d_in[3];
    const float* W1  = (const float*)d_in[4];
    const float* We1 = (const float*)d_in[5];
    const float* as1 = (const float*)d_in[6];
    const float* ad1 = (const float*)d_in[7];
    const float* ae1 = (const float*)d_in[8];
    const float* b1  = (const float*)d_in[9];
    const float* W2  = (const float*)d_in[10];
    const float* We2 = (const float*)d_in[11];
    const float* as2 = (const float*)d_in[12];
    const float* ad2 = (const float*)d_in[13];
    const float* ae2 = (const float*)d_in[14];
    const float* b2  = (const float*)d_in[15];
    const float* Wl  = (const float*)d_in[16];
    const float* bl  = (const float*)d_in[17];
    float* out = (float*)d_out;

    const int* srcp = eidx;
    const int* dstp = eidx + EE;

    __half* hhbuf; cudaGetSymbolAddress((void**)&hhbuf, d_hh);
    float*  obuf;  cudaGetSymbolAddress((void**)&obuf, d_o);

    // ---- CSR build + per-edge scalars ----
    init_k<<<(NN + 255) / 256, 256>>>(We1, ae1, We2, ae2);
    hist_k<<<(EE + 255) / 256, 256>>>(dstp);
    scan1_k<<<NBLK, 256>>>();
    scan3_k<<<NBLK, 256>>>();
    scatter_k<<<(EE + 255) / 256, 256>>>(srcp, dstp, edge_attr);

    const int warps_grid = (NN * 32 + 255) / 256;

    // ---- layer 1 ----
    gemm_fused_k<<<(NN + 127) / 128, 256>>>(x, W1, as1, ad1, hhbuf, NN, FF);
    attn_agg_k<<<warps_grid, 256>>>(b1, obuf, 0);

    // ---- layer 2 ----
    gemm_fused_k<<<(NN + 127) / 128, 256>>>(obuf, W2, as2, ad2, hhbuf, NN, HH);
    attn_agg_k<<<warps_grid, 256>>>(b2, obuf, 1);

    // ---- pool + head ----
    pool_k<<<(NN + NPB - 1) / NPB, 128>>>(obuf, batch);
    head_k<<<GG, 32>>>(Wl, bl, out);
}